// round 15
// baseline (speedup 1.0000x reference)
#include <cuda_runtime.h>

// SSIM loss: B=64, C=2, H=W=320, WIN=7 (VALID), channel-summing uniform window.
// out = 1 - mean(S), S per output pixel [64,1,314,314].
// 296 blocks (=148 SMs x 2 CTAs, one wave) over 20096 flattened output rows.
// GROUP=8: vertical writes 8 rows of 4 stats -> ONE barrier -> horizontal
// with ALL 320 threads = 8 rows x 40 x 8 cols (2 smem floats/pixel).
// Bank-conflict-free swizzle: column c stored at word c ^ (((c>>5)&1)<<2).

#define Hh 320
#define Ww 320
#define OH 314
#define OW 314
#define Bb 64
#define NBLOCKS 296
#define TOTROWS (Bb * OH)                 // 20096
#define BASE_ROWS (TOTROWS / NBLOCKS)     // 67
#define REM_ROWS (TOTROWS % NBLOCKS)      // 264
#define NPIX (64.0 * 314.0 * 314.0)
#define GROUP 8
#define NSTAT 4
#define CH_OFF (Hh * Ww)                  // channel stride (102400)
#define ROWLEN 328                        // 320 cols + 8 pad (max word 327)
#define BUFSZ (GROUP * NSTAT * ROWLEN)    // floats per buffer (10496)
#define SMEM_BYTES (2 * BUFSZ * 4)        // 83968 B (x2 CTAs = 168 kB < 228)

__device__ float g_partials[NBLOCKS];
__device__ unsigned int g_count = 0;

#define SM(buf, r, s, i) (buf)[(((r) * NSTAT + (s)) * ROWLEN) + (i)]
// swizzled word index for column c (involution; pad cols map to themselves)
#define SWZ(c) ((c) ^ ((((c) >> 5) & 1) << 2))

__global__ __launch_bounds__(320, 2) void ssim_main(
    const float* __restrict__ X, const float* __restrict__ Y,
    const float* __restrict__ data_range, const float* __restrict__ w,
    float* __restrict__ out) {
    extern __shared__ float dsm[];

    const int t = threadIdx.x;        // input column 0..319
    const int bid = blockIdx.x;       // 0..295

    const int start = bid * BASE_ROWS + min(bid, REM_ROWS);
    int left = BASE_ROWS + (bid < REM_ROWS ? 1 : 0);
    int row = start;                  // global output row

    const float w0 = w[0];            // uniform weight (1/49)
    const float K  = 1.0f / w0;       // 49
    const float cn = 49.0f / 48.0f;   // COV_NORM

    __shared__ float red[320];
    __shared__ int s_islast;

    // zero pad region (cols 320..327 -> words 320..327) of both buffers once
    if (t < 8) {
#pragma unroll
        for (int bsel = 0; bsel < 2; ++bsel)
#pragma unroll
            for (int r = 0; r < GROUP; ++r)
#pragma unroll
                for (int s = 0; s < NSTAT; ++s)
                    SM(dsm + bsel * BUFSZ, r, s, 320 + t) = 0.0f;
    }
    __syncthreads();

    // horizontal mapping: 320 threads = 8 rows x 40 groups of 8 cols
    const int hr = t / 40;            // row within group 0..7
    const int hj = t % 40;
    const int c0 = hj * 8;            // base column
    // swizzled float4 word bases (c0 multiple of 8 -> c0^f == c0+f)
    const int fa = ((c0 >> 5) & 1) << 2;
    const int fb = (((c0 + 8) >> 5) & 1) << 2;
    const int wA = c0 ^ fa;           // cols c0..c0+3
    const int wB = (c0 + 4) ^ fa;     // cols c0+4..c0+7
    const int wC = (c0 + 8) ^ fb;     // cols c0+8..c0+11
    const int wD = (c0 + 12) ^ fb;    // cols c0+12..c0+15
    // swizzled word for this thread's own column (vertical stores)
    const int tw = SWZ(t);

    float acc = 0.0f;

#pragma unroll 1
    while (left > 0) {
        const int b = row / OH;
        const int y0 = row - b * OH;
        const int seg = min(left, OH - y0);

        const float dr = data_range[b];
        const float C1 = (0.01f * dr) * (0.01f * dr);
        const float C2 = (0.03f * dr) * (0.03f * dr);
        // fold w0 out: work on raw window sums h (u = w0*h)
        const float C1p = C1 * K * K;
        const float C2p = C2 * K * K;

        const float* __restrict__ Xb = X + (size_t)b * 2 * CH_OFF;
        const float* __restrict__ Yb = Y + (size_t)b * 2 * CH_OFF;

        // 8-slot ring of RAW inputs; row k's data lives at slot k&7 (static).
        float rx0[8], rx1[8], rya[8], ryb[8];
        float vsum[NSTAT];
#pragma unroll
        for (int s = 0; s < NSTAT; ++s) vsum[s] = 0.0f;

        // prologue: input rows y0..y0+5 -> slots 0..5 (MLP 24)
        {
            int off = y0 * Ww + t;
#pragma unroll
            for (int r = 0; r < 6; ++r) {
                float x0 = Xb[off], x1 = Xb[off + CH_OFF];
                float ya = Yb[off], yb = Yb[off + CH_OFF];
                rx0[r] = x0; rx1[r] = x1; rya[r] = ya; ryb[r] = yb;
                vsum[0] += x0 + x1;
                vsum[1] += ya + yb;
                vsum[2] += fmaf(x0, x0, fmaf(x1, x1, fmaf(ya, ya, yb * yb)));
                vsum[3] += fmaf(x0, ya, x1 * yb);
                off += Ww;
            }
        }

        const int G = (seg + GROUP - 1) / GROUP;
        int offn = (y0 + 6) * Ww + t;   // running offset of next new input row

#pragma unroll 1
        for (int g = 0; g < G; ++g) {
            float* __restrict__ buf = dsm + (g & 1) * BUFSZ;

            // ---- vertical: 8 rows in two 4-row sub-batches (MLP 16 each) ----
#pragma unroll
            for (int hb = 0; hb < 2; ++hb) {
                float g4[4][4];
#pragma unroll
                for (int r = 0; r < 4; ++r) {
                    const int k = GROUP * g + hb * 4 + r;
                    if (k < seg) {
                        const int off = offn + r * Ww;
                        g4[r][0] = Xb[off]; g4[r][1] = Xb[off + CH_OFF];
                        g4[r][2] = Yb[off]; g4[r][3] = Yb[off + CH_OFF];
                    } else {
                        g4[r][0] = g4[r][1] = g4[r][2] = g4[r][3] = 0.0f;
                    }
                }
                offn += 4 * Ww;

#pragma unroll
                for (int r = 0; r < 4; ++r) {
                    const int u = hb * 4 + r;        // row slot in group (static)
                    const int k = GROUP * g + u;     // k & 7 == u (GROUP==8)
                    if (k < seg) {
                        float x0 = g4[r][0], x1 = g4[r][1];
                        float ya = g4[r][2], yb = g4[r][3];
                        vsum[0] += x0 + x1;
                        vsum[1] += ya + yb;
                        vsum[2] += fmaf(x0, x0, fmaf(x1, x1, fmaf(ya, ya, yb * yb)));
                        vsum[3] += fmaf(x0, ya, x1 * yb);
                        SM(buf, u, 0, tw) = vsum[0];
                        SM(buf, u, 1, tw) = vsum[1];
                        SM(buf, u, 2, tw) = vsum[2];
                        SM(buf, u, 3, tw) = vsum[3];
                        // retire row k (slot u), append row k+6 (slot (u+6)&7)
                        const int SO = u;                // static
                        const int SN = (u + 6) & 7;      // static
                        float o0 = rx0[SO], o1 = rx1[SO];
                        float oa = rya[SO], ob = ryb[SO];
                        vsum[0] -= o0 + o1;
                        vsum[1] -= oa + ob;
                        vsum[2] -= fmaf(o0, o0, fmaf(o1, o1, fmaf(oa, oa, ob * ob)));
                        vsum[3] -= fmaf(o0, oa, o1 * ob);
                        rx0[SN] = x0; rx1[SN] = x1;
                        rya[SN] = ya; ryb[SN] = yb;
                    }
                }
            }

            __syncthreads();   // column sums visible (only barrier per group)

            // ---- horizontal: ALL 320 threads, 8 rows x 40 x 8 cols ----
            // Reads buf[g&1]; that buffer is next written in group g+2,
            // which every thread reaches only after the NEXT barrier.
            {
                const int k = GROUP * g + hr;
                if (k < seg) {
                    float h[NSTAT][8];
#pragma unroll
                    for (int s = 0; s < NSTAT; ++s) {
                        const float4 va = *(const float4*)&SM(buf, hr, s, wA);
                        const float4 vb = *(const float4*)&SM(buf, hr, s, wB);
                        const float4 vc = *(const float4*)&SM(buf, hr, s, wC);
                        const float4 vd = *(const float4*)&SM(buf, hr, s, wD);
                        float h0 = va.x + va.y + va.z + va.w + vb.x + vb.y + vb.z;
                        float h1 = h0 - va.x + vb.w;
                        float h2 = h1 - va.y + vc.x;
                        float h3 = h2 - va.z + vc.y;
                        float h4 = h3 - va.w + vc.z;
                        float h5 = h4 - vb.x + vc.w;
                        float h6 = h5 - vb.y + vd.x;
                        float h7 = h6 - vb.z + vd.y;
                        h[s][0] = h0; h[s][1] = h1; h[s][2] = h2; h[s][3] = h3;
                        h[s][4] = h4; h[s][5] = h5; h[s][6] = h6; h[s][7] = h7;
                    }
#pragma unroll
                    for (int q = 0; q < 2; ++q) {   // two 4-px combines
                        float n[4], d[4];
#pragma unroll
                        for (int i = 0; i < 4; ++i) {
                            const int j = q * 4 + i;
                            float hx  = h[0][j];
                            float hy  = h[1][j];
                            float h23 = h[2][j];
                            float hxy = h[3][j];
                            float Pq  = hx * hy;
                            float Qq  = fmaf(hx, hx, hy * hy);
                            float A1 = 2.0f * Pq + C1p;
                            float A2 = 2.0f * cn * fmaf(K, hxy, -Pq) + C2p;
                            float B1 = Qq + C1p;
                            float B2 = cn * (fmaf(K, h23, -Qq)) + C2p;
                            bool valid = (c0 + j < OW);
                            n[i] = valid ? A1 * A2 : 0.0f;
                            d[i] = valid ? B1 * B2 : 1.0f;
                        }
                        float e0 = n[0] * d[1] + n[1] * d[0];
                        float f0 = d[0] * d[1];
                        float e1 = n[2] * d[3] + n[3] * d[2];
                        float f1 = d[2] * d[3];
                        float num = e0 * f1 + e1 * f0;
                        float den = f0 * f1;
                        acc += __fdividef(num, den);
                    }
                }
            }
        }
        __syncthreads();   // buffers reusable for next segment

        row += seg;
        left -= seg;
    }

    // ---- block reduction of acc (fixed order -> deterministic) ----
    red[t] = acc;
    __syncthreads();
    if (t < 160) red[t] += red[t + 160];
    __syncthreads();
    if (t < 80) red[t] += red[t + 80];
    __syncthreads();
    if (t < 40) red[t] += red[t + 40];
    __syncthreads();
    if (t < 20) red[t] += red[t + 20];
    __syncthreads();
    if (t < 10) red[t] += red[t + 10];
    __syncthreads();
    if (t < 5) red[t] += red[t + 5];
    __syncthreads();

    if (t == 0) {
        float v = red[0] + red[1] + red[2] + red[3] + red[4];
        g_partials[bid] = v;
        __threadfence();
        unsigned int old = atomicAdd(&g_count, 1u);
        s_islast = (old == NBLOCKS - 1);
    }
    __syncthreads();

    // ---- last block finishes the global reduction (deterministic order) ----
    if (s_islast) {
        __threadfence();
        float v = (t < NBLOCKS) ? g_partials[t] : 0.0f;
        red[t] = v;
        __syncthreads();
        if (t < 160) red[t] += red[t + 160];
        __syncthreads();
        if (t < 80) red[t] += red[t + 80];
        __syncthreads();
        if (t < 40) red[t] += red[t + 40];
        __syncthreads();
        if (t < 20) red[t] += red[t + 20];
        __syncthreads();
        if (t < 10) red[t] += red[t + 10];
        __syncthreads();
        if (t < 5) red[t] += red[t + 5];
        __syncthreads();
        if (t == 0) {
            double total = (double)(red[0] + red[1] + red[2] + red[3] + red[4]);
            out[0] = (float)(1.0 - total / NPIX);
            g_count = 0;   // reset for next graph replay
        }
    }
}

extern "C" void kernel_launch(void* const* d_in, const int* in_sizes, int n_in,
                              void* d_out, int out_size) {
    const float* X  = (const float*)d_in[0];
    const float* Y  = (const float*)d_in[1];
    const float* dr = (const float*)d_in[2];
    const float* w  = (const float*)d_in[3];
    cudaFuncSetAttribute(ssim_main, cudaFuncAttributeMaxDynamicSharedMemorySize,
                         SMEM_BYTES);
    ssim_main<<<NBLOCKS, 320, SMEM_BYTES>>>(X, Y, dr, w, (float*)d_out);
}

// round 16
// speedup vs baseline: 1.0021x; 1.0021x over previous
#include <cuda_runtime.h>

// SSIM loss: B=64, C=2, H=W=320, WIN=7 (VALID), channel-summing uniform window.
// out = 1 - mean(S), S per output pixel [64,1,314,314].
// 296 blocks (=148 SMs x 2 CTAs, one wave) over 20096 flattened output rows.
// GROUP=8: vertical writes 8 rows of 4 stats -> ONE barrier -> horizontal
// with ALL 320 threads = 8 rows x 40 x 8 cols (2 smem floats/pixel).
// Bank-conflict-free swizzle: column c stored at word c ^ (((c>>5)&1)<<2).

#define Hh 320
#define Ww 320
#define OH 314
#define OW 314
#define Bb 64
#define NBLOCKS 296
#define TOTROWS (Bb * OH)                 // 20096
#define BASE_ROWS (TOTROWS / NBLOCKS)     // 67
#define REM_ROWS (TOTROWS % NBLOCKS)      // 264
#define NPIX (64.0 * 314.0 * 314.0)
#define GROUP 8
#define NSTAT 4
#define CH_OFF (Hh * Ww)                  // channel stride (102400)
#define ROWLEN 328                        // 320 cols + 8 pad (max word 327)
#define BUFSZ (GROUP * NSTAT * ROWLEN)    // floats per buffer (10496)
#define SMEM_BYTES (2 * BUFSZ * 4)        // 83968 B (x2 CTAs = 168 kB < 228)

__device__ float g_partials[NBLOCKS];
__device__ unsigned int g_count = 0;

#define SM(buf, r, s, i) (buf)[(((r) * NSTAT + (s)) * ROWLEN) + (i)]
// swizzled word index for column c (involution; pad cols map to themselves)
#define SWZ(c) ((c) ^ ((((c) >> 5) & 1) << 2))

__global__ __launch_bounds__(320, 2) void ssim_main(
    const float* __restrict__ X, const float* __restrict__ Y,
    const float* __restrict__ data_range, const float* __restrict__ w,
    float* __restrict__ out) {
    extern __shared__ float dsm[];

    const int t = threadIdx.x;        // input column 0..319
    const int bid = blockIdx.x;       // 0..295

    const int start = bid * BASE_ROWS + min(bid, REM_ROWS);
    int left = BASE_ROWS + (bid < REM_ROWS ? 1 : 0);
    int row = start;                  // global output row

    const float w0 = w[0];            // uniform weight (1/49)
    const float K  = 1.0f / w0;       // 49
    const float cn = 49.0f / 48.0f;   // COV_NORM

    __shared__ float red[320];
    __shared__ int s_islast;

    // zero pad region (cols 320..327 -> words 320..327) of both buffers once
    if (t < 8) {
#pragma unroll
        for (int bsel = 0; bsel < 2; ++bsel)
#pragma unroll
            for (int r = 0; r < GROUP; ++r)
#pragma unroll
                for (int s = 0; s < NSTAT; ++s)
                    SM(dsm + bsel * BUFSZ, r, s, 320 + t) = 0.0f;
    }
    __syncthreads();

    // horizontal mapping: 320 threads = 8 rows x 40 groups of 8 cols
    const int hr = t / 40;            // row within group 0..7
    const int hj = t % 40;
    const int c0 = hj * 8;            // base column
    // swizzled float4 word bases (c0 multiple of 8 -> c0^f == c0+f)
    const int fa = ((c0 >> 5) & 1) << 2;
    const int fb = (((c0 + 8) >> 5) & 1) << 2;
    const int wA = c0 ^ fa;           // cols c0..c0+3
    const int wB = (c0 + 4) ^ fa;     // cols c0+4..c0+7
    const int wC = (c0 + 8) ^ fb;     // cols c0+8..c0+11
    const int wD = (c0 + 12) ^ fb;    // cols c0+12..c0+15
    // swizzled word for this thread's own column (vertical stores)
    const int tw = SWZ(t);

    float acc = 0.0f;

#pragma unroll 1
    while (left > 0) {
        const int b = row / OH;
        const int y0 = row - b * OH;
        const int seg = min(left, OH - y0);

        const float dr = data_range[b];
        const float C1 = (0.01f * dr) * (0.01f * dr);
        const float C2 = (0.03f * dr) * (0.03f * dr);
        // fold w0 out: work on raw window sums h (u = w0*h)
        const float C1p = C1 * K * K;
        const float C2p = C2 * K * K;

        const float* __restrict__ Xb = X + (size_t)b * 2 * CH_OFF;
        const float* __restrict__ Yb = Y + (size_t)b * 2 * CH_OFF;

        // 8-slot ring of RAW inputs; row k's data lives at slot k&7 (static).
        float rx0[8], rx1[8], rya[8], ryb[8];
        float vsum[NSTAT];
#pragma unroll
        for (int s = 0; s < NSTAT; ++s) vsum[s] = 0.0f;

        // prologue: input rows y0..y0+5 -> slots 0..5 (MLP 24)
        {
            int off = y0 * Ww + t;
#pragma unroll
            for (int r = 0; r < 6; ++r) {
                float x0 = Xb[off], x1 = Xb[off + CH_OFF];
                float ya = Yb[off], yb = Yb[off + CH_OFF];
                rx0[r] = x0; rx1[r] = x1; rya[r] = ya; ryb[r] = yb;
                vsum[0] += x0 + x1;
                vsum[1] += ya + yb;
                vsum[2] += fmaf(x0, x0, fmaf(x1, x1, fmaf(ya, ya, yb * yb)));
                vsum[3] += fmaf(x0, ya, x1 * yb);
                off += Ww;
            }
        }

        const int G = (seg + GROUP - 1) / GROUP;
        int offn = (y0 + 6) * Ww + t;   // running offset of next new input row

#pragma unroll 1
        for (int g = 0; g < G; ++g) {
            float* __restrict__ buf = dsm + (g & 1) * BUFSZ;

            // ---- vertical: 8 rows in two 4-row sub-batches (MLP 16 each) ----
#pragma unroll
            for (int hb = 0; hb < 2; ++hb) {
                float g4[4][4];
#pragma unroll
                for (int r = 0; r < 4; ++r) {
                    const int k = GROUP * g + hb * 4 + r;
                    if (k < seg) {
                        const int off = offn + r * Ww;
                        g4[r][0] = Xb[off]; g4[r][1] = Xb[off + CH_OFF];
                        g4[r][2] = Yb[off]; g4[r][3] = Yb[off + CH_OFF];
                    } else {
                        g4[r][0] = g4[r][1] = g4[r][2] = g4[r][3] = 0.0f;
                    }
                }
                offn += 4 * Ww;

#pragma unroll
                for (int r = 0; r < 4; ++r) {
                    const int u = hb * 4 + r;        // row slot in group (static)
                    const int k = GROUP * g + u;     // k & 7 == u (GROUP==8)
                    if (k < seg) {
                        float x0 = g4[r][0], x1 = g4[r][1];
                        float ya = g4[r][2], yb = g4[r][3];
                        vsum[0] += x0 + x1;
                        vsum[1] += ya + yb;
                        vsum[2] += fmaf(x0, x0, fmaf(x1, x1, fmaf(ya, ya, yb * yb)));
                        vsum[3] += fmaf(x0, ya, x1 * yb);
                        SM(buf, u, 0, tw) = vsum[0];
                        SM(buf, u, 1, tw) = vsum[1];
                        SM(buf, u, 2, tw) = vsum[2];
                        SM(buf, u, 3, tw) = vsum[3];
                        // retire row k (slot u), append row k+6 (slot (u+6)&7)
                        const int SO = u;                // static
                        const int SN = (u + 6) & 7;      // static
                        float o0 = rx0[SO], o1 = rx1[SO];
                        float oa = rya[SO], ob = ryb[SO];
                        vsum[0] -= o0 + o1;
                        vsum[1] -= oa + ob;
                        vsum[2] -= fmaf(o0, o0, fmaf(o1, o1, fmaf(oa, oa, ob * ob)));
                        vsum[3] -= fmaf(o0, oa, o1 * ob);
                        rx0[SN] = x0; rx1[SN] = x1;
                        rya[SN] = ya; ryb[SN] = yb;
                    }
                }
            }

            __syncthreads();   // column sums visible (only barrier per group)

            // ---- horizontal: ALL 320 threads, 8 rows x 40 x 8 cols ----
            // Reads buf[g&1]; that buffer is next written in group g+2,
            // which every thread reaches only after the NEXT barrier.
            {
                const int k = GROUP * g + hr;
                if (k < seg) {
                    float h[NSTAT][8];
#pragma unroll
                    for (int s = 0; s < NSTAT; ++s) {
                        const float4 va = *(const float4*)&SM(buf, hr, s, wA);
                        const float4 vb = *(const float4*)&SM(buf, hr, s, wB);
                        const float4 vc = *(const float4*)&SM(buf, hr, s, wC);
                        const float4 vd = *(const float4*)&SM(buf, hr, s, wD);
                        float h0 = va.x + va.y + va.z + va.w + vb.x + vb.y + vb.z;
                        float h1 = h0 - va.x + vb.w;
                        float h2 = h1 - va.y + vc.x;
                        float h3 = h2 - va.z + vc.y;
                        float h4 = h3 - va.w + vc.z;
                        float h5 = h4 - vb.x + vc.w;
                        float h6 = h5 - vb.y + vd.x;
                        float h7 = h6 - vb.z + vd.y;
                        h[s][0] = h0; h[s][1] = h1; h[s][2] = h2; h[s][3] = h3;
                        h[s][4] = h4; h[s][5] = h5; h[s][6] = h6; h[s][7] = h7;
                    }
#pragma unroll
                    for (int q = 0; q < 2; ++q) {   // two 4-px combines
                        float n[4], d[4];
#pragma unroll
                        for (int i = 0; i < 4; ++i) {
                            const int j = q * 4 + i;
                            float hx  = h[0][j];
                            float hy  = h[1][j];
                            float h23 = h[2][j];
                            float hxy = h[3][j];
                            float Pq  = hx * hy;
                            float Qq  = fmaf(hx, hx, hy * hy);
                            float A1 = 2.0f * Pq + C1p;
                            float A2 = 2.0f * cn * fmaf(K, hxy, -Pq) + C2p;
                            float B1 = Qq + C1p;
                            float B2 = cn * (fmaf(K, h23, -Qq)) + C2p;
                            bool valid = (c0 + j < OW);
                            n[i] = valid ? A1 * A2 : 0.0f;
                            d[i] = valid ? B1 * B2 : 1.0f;
                        }
                        float e0 = n[0] * d[1] + n[1] * d[0];
                        float f0 = d[0] * d[1];
                        float e1 = n[2] * d[3] + n[3] * d[2];
                        float f1 = d[2] * d[3];
                        float num = e0 * f1 + e1 * f0;
                        float den = f0 * f1;
                        acc += __fdividef(num, den);
                    }
                }
            }
        }
        __syncthreads();   // buffers reusable for next segment

        row += seg;
        left -= seg;
    }

    // ---- block reduction of acc (fixed order -> deterministic) ----
    red[t] = acc;
    __syncthreads();
    if (t < 160) red[t] += red[t + 160];
    __syncthreads();
    if (t < 80) red[t] += red[t + 80];
    __syncthreads();
    if (t < 40) red[t] += red[t + 40];
    __syncthreads();
    if (t < 20) red[t] += red[t + 20];
    __syncthreads();
    if (t < 10) red[t] += red[t + 10];
    __syncthreads();
    if (t < 5) red[t] += red[t + 5];
    __syncthreads();

    if (t == 0) {
        float v = red[0] + red[1] + red[2] + red[3] + red[4];
        g_partials[bid] = v;
        __threadfence();
        unsigned int old = atomicAdd(&g_count, 1u);
        s_islast = (old == NBLOCKS - 1);
    }
    __syncthreads();

    // ---- last block finishes the global reduction (deterministic order) ----
    if (s_islast) {
        __threadfence();
        float v = (t < NBLOCKS) ? g_partials[t] : 0.0f;
        red[t] = v;
        __syncthreads();
        if (t < 160) red[t] += red[t + 160];
        __syncthreads();
        if (t < 80) red[t] += red[t + 80];
        __syncthreads();
        if (t < 40) red[t] += red[t + 40];
        __syncthreads();
        if (t < 20) red[t] += red[t + 20];
        __syncthreads();
        if (t < 10) red[t] += red[t + 10];
        __syncthreads();
        if (t < 5) red[t] += red[t + 5];
        __syncthreads();
        if (t == 0) {
            double total = (double)(red[0] + red[1] + red[2] + red[3] + red[4]);
            out[0] = (float)(1.0 - total / NPIX);
            g_count = 0;   // reset for next graph replay
        }
    }
}

extern "C" void kernel_launch(void* const* d_in, const int* in_sizes, int n_in,
                              void* d_out, int out_size) {
    const float* X  = (const float*)d_in[0];
    const float* Y  = (const float*)d_in[1];
    const float* dr = (const float*)d_in[2];
    const float* w  = (const float*)d_in[3];
    cudaFuncSetAttribute(ssim_main, cudaFuncAttributeMaxDynamicSharedMemorySize,
                         SMEM_BYTES);
    ssim_main<<<NBLOCKS, 320, SMEM_BYTES>>>(X, Y, dr, w, (float*)d_out);
}

// round 17
// speedup vs baseline: 1.3963x; 1.3934x over previous
#include <cuda_runtime.h>

// SSIM loss: B=64, C=2, H=W=320, WIN=7 (VALID), channel-summing uniform window.
// out = 1 - mean(S), S per output pixel [64,1,314,314].
// 296 blocks (=148 SMs x 2 CTAs, one wave) over 20096 flattened output rows.
// GROUP=8: vertical writes 8 rows of 4 stats -> ONE barrier -> horizontal
// with ALL 320 threads = 8 rows x 40 x 8 cols (2 smem floats/pixel).
// Bank-conflict-free swizzle word(c) = c ^ ((c>>3)&4), register-dieted:
// only wA/wC are formed (wB=wA^4, wD=wC^4); stats 2,3 prescaled by cn*K.

#define Hh 320
#define Ww 320
#define OH 314
#define OW 314
#define Bb 64
#define NBLOCKS 296
#define TOTROWS (Bb * OH)                 // 20096
#define BASE_ROWS (TOTROWS / NBLOCKS)     // 67
#define REM_ROWS (TOTROWS % NBLOCKS)      // 264
#define NPIX (64.0 * 314.0 * 314.0)
#define GROUP 8
#define NSTAT 4
#define CH_OFF (Hh * Ww)                  // channel stride (102400)
#define ROWLEN 328                        // 320 cols + 8 pad (max word 327)
#define BUFSZ (GROUP * NSTAT * ROWLEN)    // floats per buffer (10496)
#define SMEM_BYTES (2 * BUFSZ * 4)        // 83968 B (x2 CTAs = 168 kB < 228)

__device__ float g_partials[NBLOCKS];
__device__ unsigned int g_count = 0;

#define SM(buf, r, s, i) (buf)[(((r) * NSTAT + (s)) * ROWLEN) + (i)]
// swizzled word index for column c (involution; pad cols map to themselves)
#define SWZ(c) ((c) ^ (((c) >> 3) & 4))

__global__ __launch_bounds__(320, 2) void ssim_main(
    const float* __restrict__ X, const float* __restrict__ Y,
    const float* __restrict__ data_range, const float* __restrict__ w,
    float* __restrict__ out) {
    extern __shared__ float dsm[];

    const int t = threadIdx.x;        // input column 0..319
    const int bid = blockIdx.x;       // 0..295

    const int start = bid * BASE_ROWS + min(bid, REM_ROWS);
    int left = BASE_ROWS + (bid < REM_ROWS ? 1 : 0);
    int row = start;                  // global output row

    const float w0 = w[0];            // uniform weight (1/49)
    const float K  = 1.0f / w0;       // 49
    const float cn = 49.0f / 48.0f;   // COV_NORM
    const float cnK = cn * K;         // prescale for stats 2,3

    __shared__ float red[320];
    __shared__ int s_islast;

    // zero pad region (cols 320..327 -> words 320..327) of both buffers once
    if (t < 8) {
#pragma unroll
        for (int bsel = 0; bsel < 2; ++bsel)
#pragma unroll
            for (int r = 0; r < GROUP; ++r)
#pragma unroll
                for (int s = 0; s < NSTAT; ++s)
                    SM(dsm + bsel * BUFSZ, r, s, 320 + t) = 0.0f;
    }
    __syncthreads();

    // horizontal mapping: 320 threads = 8 rows x 40 groups of 8 cols
    const int hr = t / 40;            // row within group 0..7
    const int c0 = (t % 40) * 8;      // base column
    // swizzled word for this thread's own column (vertical stores)
    const int tw = SWZ(t);

    float acc = 0.0f;

#pragma unroll 1
    while (left > 0) {
        const int b = row / OH;
        const int y0 = row - b * OH;
        const int seg = min(left, OH - y0);

        const float dr = data_range[b];
        const float C1 = (0.01f * dr) * (0.01f * dr);
        const float C2 = (0.03f * dr) * (0.03f * dr);
        // fold w0 out: all of A1,A2,B1,B2 scaled by K^2 (ratio invariant)
        const float C1p = C1 * K * K;
        const float C2p = C2 * K * K;

        const float* __restrict__ Xb = X + (size_t)b * 2 * CH_OFF;
        const float* __restrict__ Yb = Y + (size_t)b * 2 * CH_OFF;

        // 8-slot ring of RAW inputs; row k's data lives at slot k&7 (static).
        float rx0[8], rx1[8], rya[8], ryb[8];
        float vsum[NSTAT];
#pragma unroll
        for (int s = 0; s < NSTAT; ++s) vsum[s] = 0.0f;

        // prologue: input rows y0..y0+5 -> slots 0..5 (MLP 24)
        {
            int off = y0 * Ww + t;
#pragma unroll
            for (int r = 0; r < 6; ++r) {
                float x0 = Xb[off], x1 = Xb[off + CH_OFF];
                float ya = Yb[off], yb = Yb[off + CH_OFF];
                rx0[r] = x0; rx1[r] = x1; rya[r] = ya; ryb[r] = yb;
                vsum[0] += x0 + x1;
                vsum[1] += ya + yb;
                vsum[2] += fmaf(x0, x0, fmaf(x1, x1, fmaf(ya, ya, yb * yb)));
                vsum[3] += fmaf(x0, ya, x1 * yb);
                off += Ww;
            }
        }

        const int G = (seg + GROUP - 1) / GROUP;
        int offn = (y0 + 6) * Ww + t;   // running offset of next new input row

#pragma unroll 1
        for (int g = 0; g < G; ++g) {
            float* __restrict__ buf = dsm + (g & 1) * BUFSZ;

            // ---- vertical: 8 rows in two 4-row sub-batches (MLP 16 each) ----
#pragma unroll
            for (int hb = 0; hb < 2; ++hb) {
                float g4[4][4];
#pragma unroll
                for (int r = 0; r < 4; ++r) {
                    const int k = GROUP * g + hb * 4 + r;
                    if (k < seg) {
                        const int off = offn + r * Ww;
                        g4[r][0] = Xb[off]; g4[r][1] = Xb[off + CH_OFF];
                        g4[r][2] = Yb[off]; g4[r][3] = Yb[off + CH_OFF];
                    } else {
                        g4[r][0] = g4[r][1] = g4[r][2] = g4[r][3] = 0.0f;
                    }
                }
                offn += 4 * Ww;

#pragma unroll
                for (int r = 0; r < 4; ++r) {
                    const int u = hb * 4 + r;        // row slot in group (static)
                    const int k = GROUP * g + u;     // k & 7 == u (GROUP==8)
                    if (k < seg) {
                        float x0 = g4[r][0], x1 = g4[r][1];
                        float ya = g4[r][2], yb = g4[r][3];
                        vsum[0] += x0 + x1;
                        vsum[1] += ya + yb;
                        vsum[2] += fmaf(x0, x0, fmaf(x1, x1, fmaf(ya, ya, yb * yb)));
                        vsum[3] += fmaf(x0, ya, x1 * yb);
                        SM(buf, u, 0, tw) = vsum[0];
                        SM(buf, u, 1, tw) = vsum[1];
                        SM(buf, u, 2, tw) = cnK * vsum[2];   // prescaled
                        SM(buf, u, 3, tw) = cnK * vsum[3];   // prescaled
                        // retire row k (slot u), append row k+6 (slot (u+6)&7)
                        const int SO = u;                // static
                        const int SN = (u + 6) & 7;      // static
                        float o0 = rx0[SO], o1 = rx1[SO];
                        float oa = rya[SO], ob = ryb[SO];
                        vsum[0] -= o0 + o1;
                        vsum[1] -= oa + ob;
                        vsum[2] -= fmaf(o0, o0, fmaf(o1, o1, fmaf(oa, oa, ob * ob)));
                        vsum[3] -= fmaf(o0, oa, o1 * ob);
                        rx0[SN] = x0; rx1[SN] = x1;
                        rya[SN] = ya; ryb[SN] = yb;
                    }
                }
            }

            __syncthreads();   // column sums visible (only barrier per group)

            // ---- horizontal: ALL 320 threads, 8 rows x 40 x 8 cols ----
            // Reads buf[g&1]; that buffer is next written in group g+2,
            // which every thread reaches only after the NEXT barrier.
            {
                const int k = GROUP * g + hr;
                if (k < seg) {
                    // swizzled float4 word bases (recomputed: cheap, reg-free)
                    const int wA = SWZ(c0);           // cols c0..c0+3
                    const int wC = SWZ(c0 + 8);       // cols c0+8..c0+11
                    float h[NSTAT][8];
#pragma unroll
                    for (int s = 0; s < NSTAT; ++s) {
                        const float4 va = *(const float4*)&SM(buf, hr, s, wA);
                        const float4 vb = *(const float4*)&SM(buf, hr, s, wA ^ 4);
                        const float4 vc = *(const float4*)&SM(buf, hr, s, wC);
                        const float4 vd = *(const float4*)&SM(buf, hr, s, wC ^ 4);
                        float h0 = va.x + va.y + va.z + va.w + vb.x + vb.y + vb.z;
                        float h1 = h0 - va.x + vb.w;
                        float h2 = h1 - va.y + vc.x;
                        float h3 = h2 - va.z + vc.y;
                        float h4 = h3 - va.w + vc.z;
                        float h5 = h4 - vb.x + vc.w;
                        float h6 = h5 - vb.y + vd.x;
                        float h7 = h6 - vb.z + vd.y;
                        h[s][0] = h0; h[s][1] = h1; h[s][2] = h2; h[s][3] = h3;
                        h[s][4] = h4; h[s][5] = h5; h[s][6] = h6; h[s][7] = h7;
                    }
#pragma unroll
                    for (int q = 0; q < 2; ++q) {   // two 4-px combines
                        float n[4], d[4];
#pragma unroll
                        for (int i = 0; i < 4; ++i) {
                            const int j = q * 4 + i;
                            float hx  = h[0][j];
                            float hy  = h[1][j];
                            float h23 = h[2][j];     // = cnK * raw
                            float hxy = h[3][j];     // = cnK * raw
                            float Pq  = hx * hy;
                            float Qq  = fmaf(hx, hx, hy * hy);
                            float A1 = 2.0f * Pq + C1p;
                            float A2 = 2.0f * fmaf(-cn, Pq, hxy) + C2p;
                            float B1 = Qq + C1p;
                            float B2 = fmaf(-cn, Qq, h23) + C2p;
                            bool valid = (c0 + j < OW);
                            n[i] = valid ? A1 * A2 : 0.0f;
                            d[i] = valid ? B1 * B2 : 1.0f;
                        }
                        float e0 = n[0] * d[1] + n[1] * d[0];
                        float f0 = d[0] * d[1];
                        float e1 = n[2] * d[3] + n[3] * d[2];
                        float f1 = d[2] * d[3];
                        float num = e0 * f1 + e1 * f0;
                        float den = f0 * f1;
                        acc += __fdividef(num, den);
                    }
                }
            }
        }
        __syncthreads();   // buffers reusable for next segment

        row += seg;
        left -= seg;
    }

    // ---- block reduction of acc (fixed order -> deterministic) ----
    red[t] = acc;
    __syncthreads();
    if (t < 160) red[t] += red[t + 160];
    __syncthreads();
    if (t < 80) red[t] += red[t + 80];
    __syncthreads();
    if (t < 40) red[t] += red[t + 40];
    __syncthreads();
    if (t < 20) red[t] += red[t + 20];
    __syncthreads();
    if (t < 10) red[t] += red[t + 10];
    __syncthreads();
    if (t < 5) red[t] += red[t + 5];
    __syncthreads();

    if (t == 0) {
        float v = red[0] + red[1] + red[2] + red[3] + red[4];
        g_partials[bid] = v;
        __threadfence();
        unsigned int old = atomicAdd(&g_count, 1u);
        s_islast = (old == NBLOCKS - 1);
    }
    __syncthreads();

    // ---- last block finishes the global reduction (deterministic order) ----
    if (s_islast) {
        __threadfence();
        float v = (t < NBLOCKS) ? g_partials[t] : 0.0f;
        red[t] = v;
        __syncthreads();
        if (t < 160) red[t] += red[t + 160];
        __syncthreads();
        if (t < 80) red[t] += red[t + 80];
        __syncthreads();
        if (t < 40) red[t] += red[t + 40];
        __syncthreads();
        if (t < 20) red[t] += red[t + 20];
        __syncthreads();
        if (t < 10) red[t] += red[t + 10];
        __syncthreads();
        if (t < 5) red[t] += red[t + 5];
        __syncthreads();
        if (t == 0) {
            double total = (double)(red[0] + red[1] + red[2] + red[3] + red[4]);
            out[0] = (float)(1.0 - total / NPIX);
            g_count = 0;   // reset for next graph replay
        }
    }
}

extern "C" void kernel_launch(void* const* d_in, const int* in_sizes, int n_in,
                              void* d_out, int out_size) {
    const float* X  = (const float*)d_in[0];
    const float* Y  = (const float*)d_in[1];
    const float* dr = (const float*)d_in[2];
    const float* w  = (const float*)d_in[3];
    cudaFuncSetAttribute(ssim_main, cudaFuncAttributeMaxDynamicSharedMemorySize,
                         SMEM_BYTES);
    ssim_main<<<NBLOCKS, 320, SMEM_BYTES>>>(X, Y, dr, w, (float*)d_out);
}